// round 12
// baseline (speedup 1.0000x reference)
#include <cuda_runtime.h>
#include <cuda_fp16.h>
#include <math.h>

// ---------------- problem constants ----------------
#define L_    2
#define B_    32
#define T_    16
#define H_    1024
#define NCTA  128           // 32 gate rows per CTA (8 units x 4 gates)
#define ROWS  32
#define NTHREADS 256
#define DA    5             // phase-A (x-side, critical) pipeline depth
#define DB    3             // phase-B (h-side, off-critical) pipeline depth
#define RET_ELEMS (B_*T_*H_)

// per-warp staging region: phase A 5*1280=6400, phase B 3*2304=6912 -> 6912
#define WSTG  6912

// smem layout (bytes)
#define SM_W1  0            // 8 warps * 16KB resident layer-1 W (x:0-8K, h:8-16K) = 131072
#define SM_STG 131072       // 8 * 6912 = 55296 (stages; partX aliases here)
#define SM_PH  186368       // 33792 (h-side partials, dedicated)
#define SM_C   220160       // 2048
#define SM_H   222208       // 2048
#define SM_R   224256       // 1024
#define SMEM_TOTAL 225280

// ---------------- device globals (scratch; no allocs) ----------------
__device__ __half  g_Wh0[NCTA * 8 * 4096];    // pre-swizzled l0 h-side W (8 MB), 8KB/(m,w)
__device__ __half  g_xin[2][H_][B_];          // chain input, parity by n
__device__ __half  g_hst[2][L_][H_][B_];      // per-layer h state, parity by t
__device__ float   g_losspart[NCTA];
__device__ unsigned g_bar4[128];              // 4 striped counters (idx 0,32,64,96)

// ---------------- helpers ----------------
__device__ __forceinline__ unsigned su(const void* p) {
    return (unsigned)__cvta_generic_to_shared(p);
}
__device__ __forceinline__ void cp16(unsigned d, const void* s) {
    asm volatile("cp.async.cg.shared.global [%0], [%1], 16;\n" :: "r"(d), "l"(s));
}
__device__ __forceinline__ void cpcommit() { asm volatile("cp.async.commit_group;\n"); }
template <int N>
__device__ __forceinline__ void cpwaitN() { asm volatile("cp.async.wait_group %0;\n" :: "n"(N)); }

__device__ __forceinline__ void ldsm4(unsigned* r, unsigned a) {
    asm volatile("ldmatrix.sync.aligned.m8n8.x4.shared.b16 {%0,%1,%2,%3}, [%4];\n"
                 : "=r"(r[0]), "=r"(r[1]), "=r"(r[2]), "=r"(r[3]) : "r"(a));
}
__device__ __forceinline__ void ldsm4t(unsigned* r, unsigned a) {
    asm volatile("ldmatrix.sync.aligned.m8n8.x4.trans.shared.b16 {%0,%1,%2,%3}, [%4];\n"
                 : "=r"(r[0]), "=r"(r[1]), "=r"(r[2]), "=r"(r[3]) : "r"(a));
}
__device__ __forceinline__ void mma16816(float* c, const unsigned* a, const unsigned* b) {
    asm volatile("mma.sync.aligned.m16n8k16.row.col.f32.f16.f16.f32 "
                 "{%0,%1,%2,%3}, {%4,%5,%6,%7}, {%8,%9}, {%0,%1,%2,%3};\n"
                 : "+f"(c[0]), "+f"(c[1]), "+f"(c[2]), "+f"(c[3])
                 : "r"(a[0]), "r"(a[1]), "r"(a[2]), "r"(a[3]), "r"(b[0]), "r"(b[1]));
}
__device__ __forceinline__ float sigm(float v) { return 1.f / (1.f + __expf(-v)); }

// split grid barrier (striped counters)
__device__ __forceinline__ void gbar_arrive(int m) {
    __syncthreads();
    if (threadIdx.x == 0)
        asm volatile("red.release.gpu.global.add.u32 [%0], %1;\n"
                     :: "l"(&g_bar4[(m & 3) * 32]), "r"(1u));
}
__device__ __forceinline__ void gbar_wait(unsigned round) {
    if (threadIdx.x < 32) {
        const int lane = threadIdx.x;
        const unsigned need = round * 32u;
        unsigned ok;
        do {
            ok = 1u;
            if (lane < 4) {
                unsigned v;
                asm volatile("ld.acquire.gpu.global.u32 %0, [%1];"
                             : "=r"(v) : "l"(&g_bar4[lane * 32]));
                ok = (unsigned)(v >= need);
            }
        } while (__all_sync(0xffffffffu, (int)ok) == 0);
    }
    __syncthreads();
}

// convert one 32row x 128k slice (rows = this CTA's gate rows, k from kb) into
// 8 swizzled 1KB chunks: row i at byte i*32 + ((hf ^ ((i>>2)&1))*16
__device__ __forceinline__ void conv_mat(const float* __restrict__ Wsrc, int m, int kb,
                                         char* dst, int lane) {
    int srow = (lane >> 3) * 1024 + m * 8 + (lane & 7);
    const float* s0 = Wsrc + (long)srow * 1024 + kb;
    const int sw = (lane >> 2) & 1;
#pragma unroll
    for (int s = 0; s < 8; s++) {
#pragma unroll
        for (int hf = 0; hf < 2; hf++) {
            const float* src = s0 + s * 16 + hf * 8;
            float4 f0 = ((const float4*)src)[0];
            float4 f1 = ((const float4*)src)[1];
            __half2 p0 = __floats2half2_rn(f0.x, f0.y);
            __half2 p1 = __floats2half2_rn(f0.z, f0.w);
            __half2 p2 = __floats2half2_rn(f1.x, f1.y);
            __half2 p3 = __floats2half2_rn(f1.z, f1.w);
            uint4 u;
            u.x = *reinterpret_cast<unsigned*>(&p0);
            u.y = *reinterpret_cast<unsigned*>(&p1);
            u.z = *reinterpret_cast<unsigned*>(&p2);
            u.w = *reinterpret_cast<unsigned*>(&p3);
            *reinterpret_cast<uint4*>(dst + s * 1024 + lane * 32 + ((hf ^ sw) * 16)) = u;
        }
    }
}

// ---------------- h-side (off-critical) GEMM for cell n1 -> partH ----------------
__device__ __forceinline__ void run_phaseB(int n1, const char* wh0, unsigned w1su,
                                           unsigned stgsu, float* partH,
                                           int w, int lane,
                                           int aRow, int aCol, int aSel16) {
    const int t1 = n1 >> 1, l1v = n1 & 1;
    const __half* xsrc = &g_hst[t1 & 1][l1v][w * 128][0];
#pragma unroll
    for (int st = 0; st < DB - 1; st++) {
#pragma unroll
        for (int j = 0; j < 2; j++) {
            int e = lane + 32 * j, r = e >> 2, sg = e & 3;
            cp16(stgsu + st * 2304 + r * 80 + sg * 16, xsrc + (st * 16 + r) * 32 + sg * 8);
        }
        if (l1v == 0) {
            cp16(stgsu + st * 2304 + 1280 + lane * 32, wh0 + st * 1024 + lane * 32);
            cp16(stgsu + st * 2304 + 1280 + lane * 32 + 16,
                 wh0 + st * 1024 + lane * 32 + 16);
        }
        cpcommit();
    }
    float acc0[4][4], acc1[4][4];
#pragma unroll
    for (int j = 0; j < 4; j++)
#pragma unroll
        for (int q = 0; q < 4; q++) { acc0[j][q] = 0.f; acc1[j][q] = 0.f; }

#pragma unroll
    for (int s = 0; s < 8; s++) {
        const int sp = s + DB - 1;
        if (sp < 8) {
            const int p2 = sp % DB;
#pragma unroll
            for (int j = 0; j < 2; j++) {
                int e = lane + 32 * j, r = e >> 2, sg = e & 3;
                cp16(stgsu + p2 * 2304 + r * 80 + sg * 16,
                     xsrc + (sp * 16 + r) * 32 + sg * 8);
            }
            if (l1v == 0) {
                cp16(stgsu + p2 * 2304 + 1280 + lane * 32, wh0 + sp * 1024 + lane * 32);
                cp16(stgsu + p2 * 2304 + 1280 + lane * 32 + 16,
                     wh0 + sp * 1024 + lane * 32 + 16);
            }
        }
        unsigned a0[4], a1[4];
        if (l1v == 1) {
            unsigned aB = w1su + (8 + s) * 1024 + aRow * 32 + aSel16;
            ldsm4(a0, aB);
            ldsm4(a1, aB + 512);
        }
        cpcommit();
        cpwaitN<DB - 1>();
        __syncwarp();
        const int p = s % DB;
        if (l1v == 0) {
            unsigned aB = stgsu + p * 2304 + 1280 + aRow * 32 + aSel16;
            ldsm4(a0, aB);
            ldsm4(a1, aB + 512);
        }
        unsigned b0[4], b1[4];
        unsigned xB = stgsu + p * 2304 + aRow * 80 + aCol * 2;
        ldsm4t(b0, xB);
        ldsm4t(b1, xB + 32);
        mma16816(acc0[0], a0, b0 + 0); mma16816(acc0[1], a0, b0 + 2);
        mma16816(acc0[2], a0, b1 + 0); mma16816(acc0[3], a0, b1 + 2);
        mma16816(acc1[0], a1, b0 + 0); mma16816(acc1[1], a1, b0 + 2);
        mma16816(acc1[2], a1, b1 + 0); mma16816(acc1[3], a1, b1 + 2);
    }
#pragma unroll
    for (int f = 0; f < 2; f++) {
        float (*ac)[4] = f ? acc1 : acc0;
#pragma unroll
        for (int j = 0; j < 4; j++) {
            int r0 = f * 16 + (lane >> 2), col = j * 8 + (lane & 3) * 2;
            partH[(w * ROWS + r0) * 33 + col]         = ac[j][0];
            partH[(w * ROWS + r0) * 33 + col + 1]     = ac[j][1];
            partH[(w * ROWS + r0 + 8) * 33 + col]     = ac[j][2];
            partH[(w * ROWS + r0 + 8) * 33 + col + 1] = ac[j][3];
        }
    }
}

// ---------------- prep: state transposes + counter reset ----------------
__global__ void prep(const float* __restrict__ x, const float* __restrict__ h0) {
    long tid0 = (long)blockIdx.x * blockDim.x + threadIdx.x;
    long stride = (long)gridDim.x * blockDim.x;
    if (tid0 < 128) g_bar4[tid0] = 0u;
    for (long i = tid0; i < H_ * B_; i += stride) {
        int k = (int)(i >> 5), b = (int)(i & 31);
        g_xin[0][k][b] = __float2half(x[b * H_ + k]);
    }
    for (long i = tid0; i < (long)L_ * H_ * B_; i += stride) {
        int b = (int)(i & 31), k = (int)((i >> 5) & 1023), l = (int)(i >> 15);
        g_hst[0][l][k][b] = __float2half(h0[(l * B_ + b) * H_ + k]);
    }
}

// ---------------- persistent LSTM kernel ----------------
__global__ void __launch_bounds__(NTHREADS, 1)
lstm_kernel(const float* __restrict__ c0, const float* __restrict__ h0,
            const float* __restrict__ h_mask, const float* __restrict__ c_mask,
            const float* __restrict__ labels,
            const float* __restrict__ W_ih, const float* __restrict__ W_hh,
            const float* __restrict__ b_ih, const float* __restrict__ b_hh,
            float* __restrict__ out, int write_loss) {
    const int m = blockIdx.x, tid = threadIdx.x;
    const int w = tid >> 5, lane = tid & 31;

    extern __shared__ char sm_[];
    float* partX = (float*)(sm_ + SM_STG);     // aliases staging (epilogue only)
    float* partH = (float*)(sm_ + SM_PH);      // dedicated
    float* cst   = (float*)(sm_ + SM_C);
    float* hst   = (float*)(sm_ + SM_H);
    float* red   = (float*)(sm_ + SM_R);
    char*  W1w   = sm_ + SM_W1 + w * 16384;    // resident layer-1 W (x then h chunks)
    char*  STGw  = sm_ + SM_STG + w * WSTG;

    // exact fp32 state init
    for (int i = tid; i < 2 * 8 * 32; i += NTHREADS) {
        int l = i >> 8, u = (i >> 5) & 7, b = i & 31;
        int guu = m * 8 + u;
        cst[i] = c0[(l * B_ + b) * H_ + guu];
        hst[i] = h0[(l * B_ + b) * H_ + guu];
    }

    float br[2][4];
#pragma unroll
    for (int l = 0; l < 2; l++)
#pragma unroll
        for (int g = 0; g < 4; g++) {
            int idx = l * 4096 + g * 1024 + m * 8 + w;
            br[l][g] = b_ih[idx] + b_hh[idx];
        }

    const int kb = w * 128;
    const int aRow = lane & 15, aCol = (lane >> 4) * 8;
    const int aSel16 = ((lane >> 4) ^ ((aRow >> 2) & 1)) * 16;
    const unsigned w1su  = su(W1w);
    const unsigned stgsu = su(STGw);
    char* wh0w = (char*)g_Wh0 + (((long)(m * 8 + w)) << 13);

    // ---- weight conversion ----
    unsigned aWx0[8][4], aWx1[8][4];           // l0 x-side fragments (RF, 64 regs)
    conv_mat(W_ih, m, kb, W1w, lane);          // l0 x-side -> temp in W1w
    __syncwarp();
#pragma unroll
    for (int c = 0; c < 8; c++) {
        unsigned aB = w1su + c * 1024 + aRow * 32 + aSel16;
        ldsm4(aWx0[c], aB);
        ldsm4(aWx1[c], aB + 512);
    }
    __syncwarp();
    conv_mat(W_hh, m, kb, wh0w, lane);                       // l0 h-side -> global
    conv_mat(W_ih + 4096 * 1024, m, kb, W1w, lane);          // l1 x-side resident
    conv_mat(W_hh + 4096 * 1024, m, kb, W1w + 8192, lane);   // l1 h-side resident
    __threadfence();
    __syncthreads();

    float lossacc = 0.f;

    // h-side GEMM for cell 0 (initial state from prep)
    run_phaseB(0, wh0w, w1su, stgsu, partH, w, lane, aRow, aCol, aSel16);

    for (int n = 0; n < T_ * L_; n++) {
        const int t = n >> 1, l = n & 1;
        if (n) gbar_wait((unsigned)n);

        // ---- phase A: x-side GEMM (critical path), 8 k-steps ----
        const __half* xsrc = &g_xin[n & 1][w * 128][0];
#pragma unroll
        for (int st = 0; st < DA - 1; st++) {
#pragma unroll
            for (int j = 0; j < 2; j++) {
                int e = lane + 32 * j, r = e >> 2, sg = e & 3;
                cp16(stgsu + st * 1280 + r * 80 + sg * 16,
                     xsrc + (st * 16 + r) * 32 + sg * 8);
            }
            cpcommit();
        }

        // mask/label prefetch (u=w, b=lane)
        const int gu = m * 8 + w;
        const long mo = ((long)(n * B_ + lane)) * H_ + gu;
        const float hmv = __ldg(h_mask + mo);
        const float cmv = __ldg(c_mask + mo);
        float labv = 0.f;
        long ro = 0;
        if (l == 1) {
            ro = ((long)(lane * T_ + t)) * H_ + gu;
            labv = __ldg(labels + ro);
        }

        float acc0[4][4], acc1[4][4];
#pragma unroll
        for (int j = 0; j < 4; j++)
#pragma unroll
            for (int q = 0; q < 4; q++) { acc0[j][q] = 0.f; acc1[j][q] = 0.f; }

        if (l == 0) {
#pragma unroll
            for (int s = 0; s < 8; s++) {
                const int sp = s + DA - 1;
                if (sp < 8) {
                    const int p2 = sp % DA;
#pragma unroll
                    for (int j = 0; j < 2; j++) {
                        int e = lane + 32 * j, r = e >> 2, sg = e & 3;
                        cp16(stgsu + p2 * 1280 + r * 80 + sg * 16,
                             xsrc + (sp * 16 + r) * 32 + sg * 8);
                    }
                }
                cpcommit();
                cpwaitN<DA - 1>();
                __syncwarp();
                const int p = s % DA;
                unsigned b0[4], b1[4];
                unsigned xB = stgsu + p * 1280 + aRow * 80 + aCol * 2;
                ldsm4t(b0, xB);
                ldsm4t(b1, xB + 32);
                mma16816(acc0[0], aWx0[s], b0 + 0); mma16816(acc0[1], aWx0[s], b0 + 2);
                mma16816(acc0[2], aWx0[s], b1 + 0); mma16816(acc0[3], aWx0[s], b1 + 2);
                mma16816(acc1[0], aWx1[s], b0 + 0); mma16816(acc1[1], aWx1[s], b0 + 2);
                mma16816(acc1[2], aWx1[s], b1 + 0); mma16816(acc1[3], aWx1[s], b1 + 2);
            }
        } else {
#pragma unroll
            for (int s = 0; s < 8; s++) {
                const int sp = s + DA - 1;
                if (sp < 8) {
                    const int p2 = sp % DA;
#pragma unroll
                    for (int j = 0; j < 2; j++) {
                        int e = lane + 32 * j, r = e >> 2, sg = e & 3;
                        cp16(stgsu + p2 * 1280 + r * 80 + sg * 16,
                             xsrc + (sp * 16 + r) * 32 + sg * 8);
                    }
                }
                unsigned a0[4], a1[4];
                unsigned aB = w1su + s * 1024 + aRow * 32 + aSel16;
                ldsm4(a0, aB);
                ldsm4(a1, aB + 512);
                cpcommit();
                cpwaitN<DA - 1>();
                __syncwarp();
                const int p = s % DA;
                unsigned b0[4], b1[4];
                unsigned xB = stgsu + p * 1280 + aRow * 80 + aCol * 2;
                ldsm4t(b0, xB);
                ldsm4t(b1, xB + 32);
                mma16816(acc0[0], a0, b0 + 0); mma16816(acc0[1], a0, b0 + 2);
                mma16816(acc0[2], a0, b1 + 0); mma16816(acc0[3], a0, b1 + 2);
                mma16816(acc1[0], a1, b0 + 0); mma16816(acc1[1], a1, b0 + 2);
                mma16816(acc1[2], a1, b1 + 0); mma16816(acc1[3], a1, b1 + 2);
            }
        }

        // ---- partX (aliases staging) ----
        __syncthreads();
#pragma unroll
        for (int f = 0; f < 2; f++) {
            float (*ac)[4] = f ? acc1 : acc0;
#pragma unroll
            for (int j = 0; j < 4; j++) {
                int r0 = f * 16 + (lane >> 2), col = j * 8 + (lane & 3) * 2;
                partX[(w * ROWS + r0) * 33 + col]         = ac[j][0];
                partX[(w * ROWS + r0) * 33 + col + 1]     = ac[j][1];
                partX[(w * ROWS + r0 + 8) * 33 + col]     = ac[j][2];
                partX[(w * ROWS + r0 + 8) * 33 + col + 1] = ac[j][3];
            }
        }
        __syncthreads();

        // ---- cell math: thread (u=w, b=lane); gates = partX + partH + bias ----
        {
            float g[4];
#pragma unroll
            for (int gg = 0; gg < 4; gg++) {
                float ssum = 0.f;
#pragma unroll
                for (int ww = 0; ww < 8; ww++) {
                    int rr = (ww * ROWS + gg * 8 + w) * 33 + lane;
                    ssum += partX[rr] + partH[rr];
                }
                g[gg] = ssum + br[l][gg];
            }
            const int si = (l * 8 + w) * 32 + lane;
            float cold = cst[si], hold = hst[si];
            float ccand = sigm(g[1]) * cold + sigm(g[0]) * tanhf(g[2]);
            float hcand = sigm(g[3]) * tanhf(ccand);
            float cn = cmv * cold + (1.f - cmv) * ccand;
            float hn = hmv * hold + (1.f - hmv) * hcand;
            cst[si] = cn;
            hst[si] = hn;
            __half hh = __float2half(hn);
            g_xin[(n + 1) & 1][gu][lane] = hh;
            g_hst[(t & 1) ^ 1][l][gu][lane] = hh;
            if (l == 1) {
                out[ro] = hn;
                float d = hn - labv;
                lossacc += d * d;
            }
        }

        gbar_arrive(m);
        // ---- phase B for next cell (off critical path; hides in barrier slack) ----
        if (n + 1 < T_ * L_)
            run_phaseB(n + 1, wh0w, w1su, stgsu, partH, w, lane, aRow, aCol, aSel16);
    }

    // ---- deterministic loss reduction ----
    red[tid] = lossacc;
    __syncthreads();
    for (int sft = 128; sft > 0; sft >>= 1) {
        if (tid < sft) red[tid] += red[tid + sft];
        __syncthreads();
    }
    if (tid == 0) g_losspart[m] = red[0];
    gbar_arrive(m);
    gbar_wait((unsigned)(T_ * L_ + 1));
    if (m == 0 && tid == 0 && write_loss) {
        float ssum = 0.f;
        for (int i = 0; i < NCTA; i++) ssum += g_losspart[i];
        out[RET_ELEMS] = ssum / (float)RET_ELEMS;
    }
}

// ---------------- launch ----------------
extern "C" void kernel_launch(void* const* d_in, const int* in_sizes, int n_in,
                              void* d_out, int out_size) {
    const float* x      = (const float*)d_in[0];
    const float* h0     = (const float*)d_in[1];
    const float* c0     = (const float*)d_in[2];
    const float* h_mask = (const float*)d_in[3];
    const float* c_mask = (const float*)d_in[4];
    const float* labels = (const float*)d_in[5];
    const float* W_ih   = (const float*)d_in[6];
    const float* W_hh   = (const float*)d_in[7];
    const float* b_ih   = (const float*)d_in[8];
    const float* b_hh   = (const float*)d_in[9];
    float* out = (float*)d_out;

    cudaFuncSetAttribute(lstm_kernel, cudaFuncAttributeMaxDynamicSharedMemorySize,
                         SMEM_TOTAL);

    prep<<<128, 256>>>(x, h0);
    int write_loss = (out_size > RET_ELEMS) ? 1 : 0;
    lstm_kernel<<<NCTA, NTHREADS, SMEM_TOTAL>>>(c0, h0, h_mask, c_mask, labels,
                                                W_ih, W_hh, b_ih, b_hh, out,
                                                write_loss);
}

// round 13
// speedup vs baseline: 1.1966x; 1.1966x over previous
#include <cuda_runtime.h>
#include <cuda_fp16.h>
#include <math.h>

// ---------------- problem constants ----------------
#define L_    2
#define B_    32
#define T_    16
#define H_    1024
#define K_    2048
#define NCTA  128           // 32 gate rows per CTA (8 units x 4 gates)
#define ROWS  32
#define NTHREADS 256
#define KW    256           // K slice per warp
#define D_    5             // X cp.async pipeline depth (stages of k16)
#define WSTG  6400          // per-warp staging bytes (5 * 1280); partials alias [0,4224)
#define RET_ELEMS (B_*T_*H_)

// smem layout (bytes)
#define SM_W1  0                        // 8 warps * 16KB resident layer-1 W = 131072
#define SM_STG 131072                   // 8 * 6400 = 51200 (stages; warp-local partials alias)
#define SM_C   182272                   // 2048
#define SM_H   184320                   // 2048
#define SM_R   186368                   // 1024
#define SMEM_TOTAL 187392

// ---------------- device globals (scratch; no allocs) ----------------
__device__ __half  g_xin[2][H_][B_];          // chain input, parity by n
__device__ __half  g_hst[2][L_][H_][B_];      // per-layer h state, parity by t
__device__ float   g_losspart[NCTA];
__device__ unsigned g_bar;

// ---------------- helpers ----------------
__device__ __forceinline__ unsigned su(const void* p) {
    return (unsigned)__cvta_generic_to_shared(p);
}
__device__ __forceinline__ void cp16(unsigned d, const void* s) {
    asm volatile("cp.async.cg.shared.global [%0], [%1], 16;\n" :: "r"(d), "l"(s));
}
__device__ __forceinline__ void cpcommit() { asm volatile("cp.async.commit_group;\n"); }
template <int N>
__device__ __forceinline__ void cpwaitN() { asm volatile("cp.async.wait_group %0;\n" :: "n"(N)); }

__device__ __forceinline__ void ldsm4(unsigned* r, unsigned a) {
    asm volatile("ldmatrix.sync.aligned.m8n8.x4.shared.b16 {%0,%1,%2,%3}, [%4];\n"
                 : "=r"(r[0]), "=r"(r[1]), "=r"(r[2]), "=r"(r[3]) : "r"(a));
}
__device__ __forceinline__ void ldsm4t(unsigned* r, unsigned a) {
    asm volatile("ldmatrix.sync.aligned.m8n8.x4.trans.shared.b16 {%0,%1,%2,%3}, [%4];\n"
                 : "=r"(r[0]), "=r"(r[1]), "=r"(r[2]), "=r"(r[3]) : "r"(a));
}
__device__ __forceinline__ void mma16816(float* c, const unsigned* a, const unsigned* b) {
    asm volatile("mma.sync.aligned.m16n8k16.row.col.f32.f16.f16.f32 "
                 "{%0,%1,%2,%3}, {%4,%5,%6,%7}, {%8,%9}, {%0,%1,%2,%3};\n"
                 : "+f"(c[0]), "+f"(c[1]), "+f"(c[2]), "+f"(c[3])
                 : "r"(a[0]), "r"(a[1]), "r"(a[2]), "r"(a[3]), "r"(b[0]), "r"(b[1]));
}
__device__ __forceinline__ float sigm(float v) { return 1.f / (1.f + __expf(-v)); }

__device__ __forceinline__ void bar_acquire_ld(unsigned* v) {
    asm volatile("ld.acquire.gpu.global.u32 %0, [%1];" : "=r"(*v) : "l"(&g_bar));
}

// ---------------- prep: state transposes + counter reset ----------------
__global__ void prep(const float* __restrict__ x, const float* __restrict__ h0) {
    long tid0 = (long)blockIdx.x * blockDim.x + threadIdx.x;
    long stride = (long)gridDim.x * blockDim.x;
    if (tid0 == 0) g_bar = 0u;
    for (long i = tid0; i < H_ * B_; i += stride) {
        int k = (int)(i >> 5), b = (int)(i & 31);
        g_xin[0][k][b] = __float2half(x[b * H_ + k]);
    }
    for (long i = tid0; i < (long)L_ * H_ * B_; i += stride) {
        int b = (int)(i & 31), k = (int)((i >> 5) & 1023), l = (int)(i >> 15);
        g_hst[0][l][k][b] = __float2half(h0[(l * B_ + b) * H_ + k]);
    }
}

// ---------------- persistent LSTM kernel ----------------
__global__ void __launch_bounds__(NTHREADS, 1)
lstm_kernel(const float* __restrict__ c0, const float* __restrict__ h0,
            const float* __restrict__ h_mask, const float* __restrict__ c_mask,
            const float* __restrict__ labels,
            const float* __restrict__ W_ih, const float* __restrict__ W_hh,
            const float* __restrict__ b_ih, const float* __restrict__ b_hh,
            float* __restrict__ out, int write_loss) {
    const int m = blockIdx.x, tid = threadIdx.x;
    const int w = tid >> 5, lane = tid & 31;

    extern __shared__ char sm_[];
    float* cst  = (float*)(sm_ + SM_C);
    float* hst  = (float*)(sm_ + SM_H);
    float* red  = (float*)(sm_ + SM_R);
    char*  W1w  = sm_ + SM_W1 + w * 16384;     // warp-private resident layer-1 W
    char*  STGw = sm_ + SM_STG + w * WSTG;     // warp-private X staging (+partials alias)

    // exact fp32 state init for this CTA's 8 units, both layers
    for (int i = tid; i < 2 * 8 * 32; i += NTHREADS) {
        int l = i >> 8, u = (i >> 5) & 7, b = i & 31;
        int guu = m * 8 + u;
        cst[i] = c0[(l * B_ + b) * H_ + guu];
        hst[i] = h0[(l * B_ + b) * H_ + guu];
    }

    // bias regs for thread's unit (u = w): br[l][gate]
    float br[2][4];
#pragma unroll
    for (int l = 0; l < 2; l++)
#pragma unroll
        for (int g = 0; g < 4; g++) {
            int idx = l * 4096 + g * 1024 + m * 8 + w;
            br[l][g] = b_ih[idx] + b_hh[idx];
        }

    const int k0 = w * KW;
    const int aRow = lane & 15, aCol = (lane >> 4) * 8;
    const int aSel16 = ((lane >> 4) ^ ((aRow >> 2) & 1)) * 16;
    const unsigned w1su  = su(W1w);
    const unsigned stgsu = su(STGw);

    // ---- weight convert fp32->fp16 into swizzled SMEM chunks ----
    // chunk s (1024B, 32 rows): row i at byte i*32 + (hf ^ ((i>>2)&1))*16
    unsigned aW0[16][4], aW1[16][4];   // layer-0 A fragments (RF-resident)
    {
        const int kb = (w & 3) * 256;
        const int s_ = lane >> 1, hf = lane & 1;
        const float* base = (w < 4) ? W_ih : W_hh;
#pragma unroll 1
        for (int l = 0; l < 2; l++) {
            const float* Wsrc = base + (long)l * 4096 * 1024;
#pragma unroll
            for (int i = 0; i < 32; i++) {
                int srow = (i >> 3) * 1024 + m * 8 + (i & 7);
                const float* src = Wsrc + (long)srow * 1024 + kb + s_ * 16 + hf * 8;
                float4 f0 = ((const float4*)src)[0];
                float4 f1 = ((const float4*)src)[1];
                __half2 p0 = __floats2half2_rn(f0.x, f0.y);
                __half2 p1 = __floats2half2_rn(f0.z, f0.w);
                __half2 p2 = __floats2half2_rn(f1.x, f1.y);
                __half2 p3 = __floats2half2_rn(f1.z, f1.w);
                uint4 u;
                u.x = *reinterpret_cast<unsigned*>(&p0);
                u.y = *reinterpret_cast<unsigned*>(&p1);
                u.z = *reinterpret_cast<unsigned*>(&p2);
                u.w = *reinterpret_cast<unsigned*>(&p3);
                *reinterpret_cast<uint4*>(
                    W1w + s_ * 1024 + i * 32 + (hf ^ ((i >> 2) & 1)) * 16) = u;
            }
            __syncwarp();
            if (l == 0) {
#pragma unroll
                for (int s = 0; s < 16; s++) {
                    unsigned aB = w1su + s * 1024 + aRow * 32 + aSel16;
                    ldsm4(aW0[s], aB);
                    ldsm4(aW1[s], aB + 512);
                }
                __syncwarp();
            }
        }
    }
    __syncthreads();

    float lossacc = 0.f;

    for (int n = 0; n < T_ * L_; n++) {
        const int t = n >> 1, l = n & 1;
        const bool xside = (w < 4);

        // ---- dependency-aware wait: ONLY x-side warps wait for flag(n-1).
        // h-side input (h_l(t-1)) was published 2 cells ago -> already visible.
        if (xside && n) {
            const unsigned need = (unsigned)n * NCTA;
            if (lane == 0) {
                unsigned v;
                do { bar_acquire_ld(&v); } while (v < need);
            }
            __syncwarp();
            unsigned v2;                 // per-lane acquire for ordering
            bar_acquire_ld(&v2);
        }

        const __half* xsrc = xside ? &g_xin[n & 1][k0][0]
                                   : &g_hst[t & 1][l][k0 - 1024][0];

        // X prologue: stages 0..D-2
#pragma unroll
        for (int st = 0; st < D_ - 1; st++) {
#pragma unroll
            for (int j = 0; j < 2; j++) {
                int e = lane + 32 * j, r = e >> 2, sg = e & 3;
                cp16(stgsu + st * 1280 + r * 80 + sg * 16,
                     xsrc + (st * 16 + r) * 32 + sg * 8);
            }
            cpcommit();
        }

        // prefetch masks/labels for thread's (u=w, b=lane)
        const int gu = m * 8 + w;
        const long mo = ((long)(n * B_ + lane)) * H_ + gu;
        const float hmv = __ldg(h_mask + mo);
        const float cmv = __ldg(c_mask + mo);
        float labv = 0.f;
        long ro = 0;
        if (l == 1) {
            ro = ((long)(lane * T_ + t)) * H_ + gu;
            labv = __ldg(labels + ro);
        }

        float acc0[4][4], acc1[4][4];
#pragma unroll
        for (int j = 0; j < 4; j++)
#pragma unroll
            for (int q = 0; q < 4; q++) { acc0[j][q] = 0.f; acc1[j][q] = 0.f; }

        if (l == 0) {
            // A from registers
#pragma unroll
            for (int s = 0; s < 16; s++) {
                const int sp = s + D_ - 1;
                if (sp < 16) {
                    const int p2 = sp % D_;
#pragma unroll
                    for (int j = 0; j < 2; j++) {
                        int e = lane + 32 * j, r = e >> 2, sg = e & 3;
                        cp16(stgsu + p2 * 1280 + r * 80 + sg * 16,
                             xsrc + (sp * 16 + r) * 32 + sg * 8);
                    }
                }
                cpcommit();
                cpwaitN<D_ - 1>();
                __syncwarp();
                const int p = s % D_;
                unsigned b0[4], b1[4];
                unsigned xB = stgsu + p * 1280 + aRow * 80 + aCol * 2;
                ldsm4t(b0, xB);
                ldsm4t(b1, xB + 32);
                mma16816(acc0[0], aW0[s], b0 + 0); mma16816(acc0[1], aW0[s], b0 + 2);
                mma16816(acc0[2], aW0[s], b1 + 0); mma16816(acc0[3], aW0[s], b1 + 2);
                mma16816(acc1[0], aW1[s], b0 + 0); mma16816(acc1[1], aW1[s], b0 + 2);
                mma16816(acc1[2], aW1[s], b1 + 0); mma16816(acc1[3], aW1[s], b1 + 2);
            }
        } else {
            // A from resident SMEM
#pragma unroll
            for (int s = 0; s < 16; s++) {
                const int sp = s + D_ - 1;
                if (sp < 16) {
                    const int p2 = sp % D_;
#pragma unroll
                    for (int j = 0; j < 2; j++) {
                        int e = lane + 32 * j, r = e >> 2, sg = e & 3;
                        cp16(stgsu + p2 * 1280 + r * 80 + sg * 16,
                             xsrc + (sp * 16 + r) * 32 + sg * 8);
                    }
                }
                unsigned a0[4], a1[4];
                unsigned aB = w1su + s * 1024 + aRow * 32 + aSel16;
                ldsm4(a0, aB);
                ldsm4(a1, aB + 512);
                cpcommit();
                cpwaitN<D_ - 1>();
                __syncwarp();
                const int p = s % D_;
                unsigned b0[4], b1[4];
                unsigned xB = stgsu + p * 1280 + aRow * 80 + aCol * 2;
                ldsm4t(b0, xB);
                ldsm4t(b1, xB + 32);
                mma16816(acc0[0], a0, b0 + 0); mma16816(acc0[1], a0, b0 + 2);
                mma16816(acc0[2], a0, b1 + 0); mma16816(acc0[3], a0, b1 + 2);
                mma16816(acc1[0], a1, b0 + 0); mma16816(acc1[1], a1, b0 + 2);
                mma16816(acc1[2], a1, b1 + 0); mma16816(acc1[3], a1, b1 + 2);
            }
        }

        // ---- partials: WARP-LOCAL region (aliases own staging; no pre-sync) ----
        {
            float* pw = (float*)STGw;
#pragma unroll
            for (int f = 0; f < 2; f++) {
                float (*ac)[4] = f ? acc1 : acc0;
#pragma unroll
                for (int j = 0; j < 4; j++) {
                    int r0 = f * 16 + (lane >> 2), col = j * 8 + (lane & 3) * 2;
                    pw[r0 * 33 + col]           = ac[j][0];
                    pw[r0 * 33 + col + 1]       = ac[j][1];
                    pw[(r0 + 8) * 33 + col]     = ac[j][2];
                    pw[(r0 + 8) * 33 + col + 1] = ac[j][3];
                }
            }
        }
        __syncthreads();

        // ---- cell math: thread (u=w, b=lane) ----
        {
            float g[4];
#pragma unroll
            for (int gg = 0; gg < 4; gg++) {
                float ssum = 0.f;
#pragma unroll
                for (int ww = 0; ww < 8; ww++)
                    ssum += ((float*)(sm_ + SM_STG + ww * WSTG))[(gg * 8 + w) * 33 + lane];
                g[gg] = ssum + br[l][gg];
            }
            const int si = (l * 8 + w) * 32 + lane;
            float cold = cst[si], hold = hst[si];
            float ccand = sigm(g[1]) * cold + sigm(g[0]) * tanhf(g[2]);
            float hcand = sigm(g[3]) * tanhf(ccand);
            float cn = cmv * cold + (1.f - cmv) * ccand;
            float hn = hmv * hold + (1.f - hmv) * hcand;
            cst[si] = cn;
            hst[si] = hn;
            __half hh = __float2half(hn);
            g_xin[(n + 1) & 1][gu][lane] = hh;
            g_hst[(t & 1) ^ 1][l][gu][lane] = hh;
            if (l == 1) {
                out[ro] = hn;
                float d = hn - labv;
                lossacc += d * d;
            }
        }
        __syncthreads();            // partial reads + h stores complete CTA-wide
        if (tid == 0)
            asm volatile("red.release.gpu.global.add.u32 [%0], %1;\n"
                         :: "l"(&g_bar), "r"(1u));
        // h-side warps of cell n+1 proceed immediately (their input is 2 cells old);
        // x-side warps will spin on the flag at the top of the next iteration.
    }

    // ---- deterministic loss reduction ----
    red[tid] = lossacc;
    __syncthreads();
    for (int sft = 128; sft > 0; sft >>= 1) {
        if (tid < sft) red[tid] += red[tid + sft];
        __syncthreads();
    }
    if (tid == 0) {
        g_losspart[m] = red[0];
        asm volatile("red.release.gpu.global.add.u32 [%0], %1;\n"
                     :: "l"(&g_bar), "r"(1u));
        if (m == 0 && write_loss) {
            const unsigned need = (unsigned)(T_ * L_ + 1) * NCTA;
            unsigned v;
            do { bar_acquire_ld(&v); } while (v < need);
            float ssum = 0.f;
            for (int i = 0; i < NCTA; i++) ssum += g_losspart[i];
            out[RET_ELEMS] = ssum / (float)RET_ELEMS;
        }
    }
}

// ---------------- launch ----------------
extern "C" void kernel_launch(void* const* d_in, const int* in_sizes, int n_in,
                              void* d_out, int out_size) {
    const float* x      = (const float*)d_in[0];
    const float* h0     = (const float*)d_in[1];
    const float* c0     = (const float*)d_in[2];
    const float* h_mask = (const float*)d_in[3];
    const float* c_mask = (const float*)d_in[4];
    const float* labels = (const float*)d_in[5];
    const float* W_ih   = (const float*)d_in[6];
    const float* W_hh   = (const float*)d_in[7];
    const float* b_ih   = (const float*)d_in[8];
    const float* b_hh   = (const float*)d_in[9];
    float* out = (float*)d_out;

    cudaFuncSetAttribute(lstm_kernel, cudaFuncAttributeMaxDynamicSharedMemorySize,
                         SMEM_TOTAL);

    prep<<<128, 256>>>(x, h0);
    int write_loss = (out_size > RET_ELEMS) ? 1 : 0;
    lstm_kernel<<<NCTA, NTHREADS, SMEM_TOTAL>>>(c0, h0, h_mask, c_mask, labels,
                                                W_ih, W_hh, b_ih, b_hh, out,
                                                write_loss);
}